// round 2
// baseline (speedup 1.0000x reference)
#include <cuda_runtime.h>
#include <cuda_bf16.h>
#include <cstdint>

// Problem constants
#define BATCH 8
#define NQ    2048
#define NS    4096
#define DIM   512

// GEMM tiling
#define BM 128
#define BN 128
#define BK 64
#define LDA 520          // 512 + 8 pad (conflict-free ldmatrix: 1040B stride ≡ 4 banks)
#define LDB 72           // 64 + 8 pad  (144B stride ≡ 4 banks)
#define NKC (DIM / BK)   // 8 k-chunks
#define KSTEPS (BK / 16) // 4 mma k-steps per chunk

#define A_SMEM_BYTES (BM * LDA * 2)            // 133120
#define B_SMEM_BYTES (2 * BN * LDB * 2)        // 36864
#define RM_OFF (A_SMEM_BYTES + B_SMEM_BYTES)   // 169984
#define SMEM_TOTAL (RM_OFF + BM * 4)           // 170496

// Device scratch (no allocations allowed)
__device__ __nv_bfloat16 g_qn[(size_t)BATCH * NQ * DIM];
__device__ __nv_bfloat16 g_sn[(size_t)BATCH * NS * DIM];
__device__ float         g_maxdot[(size_t)BATCH * NQ];

// ---------------------------------------------------------------------------
// monotone float <-> uint mapping for atomicMax on floats
// ---------------------------------------------------------------------------
__device__ __forceinline__ unsigned fkey(float f) {
    unsigned u = __float_as_uint(f);
    return (u & 0x80000000u) ? ~u : (u | 0x80000000u);
}
__device__ __forceinline__ float funkey(unsigned k) {
    unsigned u = (k & 0x80000000u) ? (k ^ 0x80000000u) : ~k;
    return __uint_as_float(u);
}

// ---------------------------------------------------------------------------
// Normalize: one warp per row of 512 fp32 -> bf16 (x / max(||x||, eps))
// ---------------------------------------------------------------------------
__device__ __forceinline__ void normalize_rows_impl(
    const float* __restrict__ in, __nv_bfloat16* __restrict__ out, int nrows)
{
    int row = blockIdx.x * (blockDim.x >> 5) + (threadIdx.x >> 5);
    if (row >= nrows) return;
    int lane = threadIdx.x & 31;

    const float4* rin = reinterpret_cast<const float4*>(in + (size_t)row * DIM);
    float4 v[4];
    float s = 0.f;
#pragma unroll
    for (int j = 0; j < 4; j++) {
        v[j] = rin[j * 32 + lane];
        s += v[j].x * v[j].x + v[j].y * v[j].y + v[j].z * v[j].z + v[j].w * v[j].w;
    }
#pragma unroll
    for (int o = 16; o > 0; o >>= 1) s += __shfl_xor_sync(0xFFFFFFFFu, s, o);

    float inv = 1.0f / fmaxf(sqrtf(s), 1e-12f);

    __nv_bfloat16* orow = out + (size_t)row * DIM;
#pragma unroll
    for (int j = 0; j < 4; j++) {
        __nv_bfloat162 h0 = __floats2bfloat162_rn(v[j].x * inv, v[j].y * inv);
        __nv_bfloat162 h1 = __floats2bfloat162_rn(v[j].z * inv, v[j].w * inv);
        uint2 pk;
        pk.x = *reinterpret_cast<unsigned*>(&h0);
        pk.y = *reinterpret_cast<unsigned*>(&h1);
        *reinterpret_cast<uint2*>(orow + (size_t)(j * 32 + lane) * 4) = pk;
    }
}

__global__ void normalize_q_kernel(const float* __restrict__ in) {
    normalize_rows_impl(in, g_qn, BATCH * NQ);
}
__global__ void normalize_s_kernel(const float* __restrict__ in) {
    normalize_rows_impl(in, g_sn, BATCH * NS);
}

// ---------------------------------------------------------------------------
// cp.async helpers
// ---------------------------------------------------------------------------
__device__ __forceinline__ void cp_async16(unsigned saddr, const void* gptr) {
    asm volatile("cp.async.cg.shared.global [%0], [%1], 16;\n" :: "r"(saddr), "l"(gptr));
}
__device__ __forceinline__ void cp_commit() {
    asm volatile("cp.async.commit_group;\n" ::: "memory");
}
template <int N>
__device__ __forceinline__ void cp_wait() {
    asm volatile("cp.async.wait_group %0;\n" :: "n"(N) : "memory");
}

// ---------------------------------------------------------------------------
// Main: one block per (batch, q-tile of 128). Query tile resident in SMEM,
// support streamed (cp.async double buffer), bf16 mma.sync, running row-max.
// ---------------------------------------------------------------------------
__global__ __launch_bounds__(256, 1) void gemm_max_kernel()
{
    extern __shared__ char smem[];
    __nv_bfloat16* As = reinterpret_cast<__nv_bfloat16*>(smem);
    __nv_bfloat16* Bs = reinterpret_cast<__nv_bfloat16*>(smem + A_SMEM_BYTES);
    unsigned* rowmaxU = reinterpret_cast<unsigned*>(smem + RM_OFF);

    const int b   = blockIdx.x >> 4;   // 16 q-tiles per batch
    const int qt  = blockIdx.x & 15;
    const int tid = threadIdx.x;
    const int lane = tid & 31;
    const int wid  = tid >> 5;
    const int wm = (wid >> 2) * 64;    // warp row offset (2 rows of warps)
    const int wn = (wid & 3) * 32;     // warp col offset (4 cols of warps)

    // ---- load full A (query) tile: 128 x 512 bf16 ----
    const uint4* gA = reinterpret_cast<const uint4*>(
        g_qn + ((size_t)(b * NQ + qt * BM)) * DIM);
#pragma unroll
    for (int i = 0; i < 32; i++) {
        int idx = tid + i * 256;       // 0..8191
        int r = idx >> 6;              // 64 uint4 per row
        int c = idx & 63;
        uint4 v = gA[idx];
        *reinterpret_cast<uint4*>(As + r * LDA + c * 8) = v;
    }
    if (tid < BM) rowmaxU[tid] = 0u;   // key 0 == minimal
    __syncthreads();

    const unsigned aBase = (unsigned)__cvta_generic_to_shared(As);
    const unsigned bBase = (unsigned)__cvta_generic_to_shared(Bs);

    float rmax[4][2];
#pragma unroll
    for (int mi = 0; mi < 4; mi++) { rmax[mi][0] = -1e30f; rmax[mi][1] = -1e30f; }

    const __nv_bfloat16* gB0 = g_sn + (size_t)b * NS * DIM;

    for (int st = 0; st < NS / BN; st++) {
        float C[4][4][4];
#pragma unroll
        for (int mi = 0; mi < 4; mi++)
#pragma unroll
            for (int ni = 0; ni < 4; ni++)
#pragma unroll
                for (int e = 0; e < 4; e++) C[mi][ni][e] = 0.f;

        // issue chunk 0 -> buffer 0
        {
#pragma unroll
            for (int i = 0; i < 4; i++) {
                int idx = tid + i * 256;        // 0..1023
                int r = idx >> 3;               // 8 uint4 per row
                int c = idx & 7;
                const void* g = gB0 + ((size_t)(st * BN + r)) * DIM + 0 * BK + c * 8;
                cp_async16(bBase + (unsigned)((r * LDB + c * 8) * 2), g);
            }
            cp_commit();
        }

        for (int kc = 0; kc < NKC; kc++) {
            if (kc < NKC - 1) {
                int buf = (kc + 1) & 1;
#pragma unroll
                for (int i = 0; i < 4; i++) {
                    int idx = tid + i * 256;
                    int r = idx >> 3;
                    int c = idx & 7;
                    const void* g = gB0 + ((size_t)(st * BN + r)) * DIM + (kc + 1) * BK + c * 8;
                    cp_async16(bBase + (unsigned)((buf * BN * LDB + r * LDB + c * 8) * 2), g);
                }
                cp_commit();
                cp_wait<1>();
            } else {
                cp_wait<0>();
            }
            __syncthreads();

            const int buf = kc & 1;
#pragma unroll
            for (int ks = 0; ks < KSTEPS; ks++) {
                // A fragments: 4 m-tiles of 16x16
                unsigned afr[4][4];
#pragma unroll
                for (int mi = 0; mi < 4; mi++) {
                    unsigned addr = aBase + (unsigned)(((wm + mi * 16 + (lane & 15)) * LDA
                                    + kc * BK + ks * 16 + (lane >> 4) * 8) * 2);
                    asm volatile("ldmatrix.sync.aligned.m8n8.x4.shared.b16 {%0,%1,%2,%3}, [%4];"
                                 : "=r"(afr[mi][0]), "=r"(afr[mi][1]),
                                   "=r"(afr[mi][2]), "=r"(afr[mi][3])
                                 : "r"(addr));
                }
                // B fragments: 4 n-tiles of 8 (n) x 16 (k)
                unsigned bfr[4][2];
#pragma unroll
                for (int ni = 0; ni < 4; ni++) {
                    int n = wn + ni * 8 + (lane & 7);
                    unsigned addr = bBase + (unsigned)(((buf * BN * LDB) + n * LDB
                                    + ks * 16 + ((lane >> 3) & 1) * 8) * 2);
                    asm volatile("ldmatrix.sync.aligned.m8n8.x2.shared.b16 {%0,%1}, [%2];"
                                 : "=r"(bfr[ni][0]), "=r"(bfr[ni][1])
                                 : "r"(addr));
                }
#pragma unroll
                for (int mi = 0; mi < 4; mi++)
#pragma unroll
                    for (int ni = 0; ni < 4; ni++) {
                        asm volatile(
                            "mma.sync.aligned.m16n8k16.row.col.f32.bf16.bf16.f32 "
                            "{%0,%1,%2,%3}, {%4,%5,%6,%7}, {%8,%9}, {%0,%1,%2,%3};"
                            : "+f"(C[mi][ni][0]), "+f"(C[mi][ni][1]),
                              "+f"(C[mi][ni][2]), "+f"(C[mi][ni][3])
                            : "r"(afr[mi][0]), "r"(afr[mi][1]),
                              "r"(afr[mi][2]), "r"(afr[mi][3]),
                              "r"(bfr[ni][0]), "r"(bfr[ni][1]));
                    }
            }
            __syncthreads();
        }

        // fold this s-tile into running row maxes
#pragma unroll
        for (int mi = 0; mi < 4; mi++) {
            float m0 = rmax[mi][0], m1 = rmax[mi][1];
#pragma unroll
            for (int ni = 0; ni < 4; ni++) {
                m0 = fmaxf(m0, fmaxf(C[mi][ni][0], C[mi][ni][1]));
                m1 = fmaxf(m1, fmaxf(C[mi][ni][2], C[mi][ni][3]));
            }
            rmax[mi][0] = m0; rmax[mi][1] = m1;
        }
    }

    // epilogue: combine per-row maxes across the 4 lane-groups and 4 n-warps
#pragma unroll
    for (int mi = 0; mi < 4; mi++) {
#pragma unroll
        for (int g = 0; g < 2; g++) {
            int row = wm + mi * 16 + (lane >> 2) + g * 8;
            atomicMax(&rowmaxU[row], fkey(rmax[mi][g]));
        }
    }
    __syncthreads();
    if (tid < BM) {
        g_maxdot[(size_t)b * NQ + qt * BM + tid] = funkey(rowmaxU[tid]);
    }
}

// ---------------------------------------------------------------------------
// Finalize: out[b] = mean over q of (1 - maxdot)
// ---------------------------------------------------------------------------
__global__ void finalize_kernel(float* __restrict__ out)
{
    __shared__ float red[256];
    int b = blockIdx.x;
    float s = 0.f;
    for (int i = threadIdx.x; i < NQ; i += 256)
        s += 1.0f - g_maxdot[(size_t)b * NQ + i];
    red[threadIdx.x] = s;
    __syncthreads();
#pragma unroll
    for (int o = 128; o > 0; o >>= 1) {
        if (threadIdx.x < o) red[threadIdx.x] += red[threadIdx.x + o];
        __syncthreads();
    }
    if (threadIdx.x == 0) out[b] = red[0] * (1.0f / NQ);
}

// ---------------------------------------------------------------------------
extern "C" void kernel_launch(void* const* d_in, const int* in_sizes, int n_in,
                              void* d_out, int out_size)
{
    const float* q = (const float*)d_in[0];
    const float* s = (const float*)d_in[1];
    float* out = (float*)d_out;

    cudaFuncSetAttribute(gemm_max_kernel,
                         cudaFuncAttributeMaxDynamicSharedMemorySize, SMEM_TOTAL);

    // 8 warps/block -> 8 rows per block
    normalize_q_kernel<<<(BATCH * NQ + 7) / 8, 256>>>(q);
    normalize_s_kernel<<<(BATCH * NS + 7) / 8, 256>>>(s);
    gemm_max_kernel<<<BATCH * (NQ / BM), 256, SMEM_TOTAL>>>();
    finalize_kernel<<<BATCH, 256>>>(out);
}

// round 4
// speedup vs baseline: 1.2509x; 1.2509x over previous
#include <cuda_runtime.h>
#include <cuda_bf16.h>
#include <cstdint>

// Problem constants
#define BATCH 8
#define NQ    2048
#define NS    4096
#define DIM   512

// Tiling
#define BM 128
#define BN 128
#define BK 128
#define NCHUNK ((NS / BN) * (DIM / BK))   // 32 stiles * 4 kchunks = 128
#define NBUF 3

#define A_BYTES    (BM * DIM * 2)         // 131072 = 8 chunks of 16KB (64 cols each)
#define BBUF_BYTES (BN * BK * 2)          // 32768  = 2 sub-chunks of 16KB
#define RM_OFF     (A_BYTES + NBUF * BBUF_BYTES)   // 229376
#define SMEM_TOTAL (RM_OFF + BM * 4)               // 229888

// Device scratch
__device__ __nv_bfloat16 g_qn[(size_t)BATCH * NQ * DIM];
__device__ __nv_bfloat16 g_sn[(size_t)BATCH * NS * DIM];
__device__ float         g_maxdot[(size_t)BATCH * NQ];

// ---------------------------------------------------------------------------
// helpers
// ---------------------------------------------------------------------------
__device__ __forceinline__ uint32_t swz(uint32_t x) {   // SW128: bits[6:4] ^= bits[9:7]
    return x ^ ((x >> 3) & 0x70);
}
__device__ __forceinline__ void cp_async16(uint32_t saddr, const void* gptr) {
    asm volatile("cp.async.cg.shared.global [%0], [%1], 16;\n" :: "r"(saddr), "l"(gptr));
}
__device__ __forceinline__ void cp_commit() {
    asm volatile("cp.async.commit_group;\n" ::: "memory");
}
template <int N>
__device__ __forceinline__ void cp_wait() {
    asm volatile("cp.async.wait_group %0;\n" :: "n"(N) : "memory");
}
__device__ __forceinline__ unsigned fkey(float f) {
    unsigned u = __float_as_uint(f);
    return (u & 0x80000000u) ? ~u : (u | 0x80000000u);
}
__device__ __forceinline__ float funkey(unsigned k) {
    unsigned u = (k & 0x80000000u) ? (k ^ 0x80000000u) : ~k;
    return __uint_as_float(u);
}

// ---------------------------------------------------------------------------
// Normalize: one warp per row of 512 fp32 -> bf16
// ---------------------------------------------------------------------------
__device__ __forceinline__ void normalize_row(const float* __restrict__ rinF,
                                              __nv_bfloat16* __restrict__ orow, int lane)
{
    const float4* rin = reinterpret_cast<const float4*>(rinF);
    float4 v[4];
    float s = 0.f;
#pragma unroll
    for (int j = 0; j < 4; j++) {
        v[j] = rin[j * 32 + lane];
        s += v[j].x * v[j].x + v[j].y * v[j].y + v[j].z * v[j].z + v[j].w * v[j].w;
    }
#pragma unroll
    for (int o = 16; o > 0; o >>= 1) s += __shfl_xor_sync(0xFFFFFFFFu, s, o);
    float inv = 1.0f / fmaxf(sqrtf(s), 1e-12f);
#pragma unroll
    for (int j = 0; j < 4; j++) {
        __nv_bfloat162 h0 = __floats2bfloat162_rn(v[j].x * inv, v[j].y * inv);
        __nv_bfloat162 h1 = __floats2bfloat162_rn(v[j].z * inv, v[j].w * inv);
        uint2 pk;
        pk.x = *reinterpret_cast<unsigned*>(&h0);
        pk.y = *reinterpret_cast<unsigned*>(&h1);
        *reinterpret_cast<uint2*>(orow + (size_t)(j * 32 + lane) * 4) = pk;
    }
}

__global__ void normalize_all_kernel(const float* __restrict__ q,
                                     const float* __restrict__ s)
{
    int row = blockIdx.x * (blockDim.x >> 5) + (threadIdx.x >> 5);
    int lane = threadIdx.x & 31;
    const int nq = BATCH * NQ;
    const int ntot = nq + BATCH * NS;
    if (row >= ntot) return;
    if (row < nq)
        normalize_row(q + (size_t)row * DIM, g_qn + (size_t)row * DIM, lane);
    else {
        int r = row - nq;
        normalize_row(s + (size_t)r * DIM, g_sn + (size_t)r * DIM, lane);
    }
}

// ---------------------------------------------------------------------------
// B chunk fill: chunk ci covers support rows [st*128, st*128+128), k-cols
// [kc*128, kc*128+128). 2048 x 16B segments, 8 per thread (256 threads).
// ---------------------------------------------------------------------------
__device__ __forceinline__ void fill_b_chunk(uint32_t smem_u32,
                                             const __nv_bfloat16* __restrict__ gB,
                                             int ci, int tid)
{
    const int st = ci >> 2;
    const int kc = ci & 3;
    const uint32_t bb = A_BYTES + (uint32_t)(ci % NBUF) * BBUF_BYTES;
#pragma unroll
    for (int i = 0; i < 8; i++) {
        int idx = tid + i * 256;         // 0..2047
        int r = idx >> 4;                // 16 segs per row
        int rest = idx & 15;
        int sub = rest >> 3;             // 64-col half
        int s8 = rest & 7;
        const void* src = gB + (size_t)(st * BN + r) * DIM + kc * BK + sub * 64 + s8 * 8;
        cp_async16(smem_u32 + bb + sub * 16384 + swz((uint32_t)(r * 128 + s8 * 16)), src);
    }
    cp_commit();
}

// ---------------------------------------------------------------------------
// GEMM-max: one block per (batch, q-tile). A resident (swizzled), B 3-buffer
// depth-2 cp.async pipeline, one __syncthreads per 128-wide k-chunk.
// 8 warps, warp tile 64x32 (2x4 warp grid), mma.sync m16n8k16 bf16.
// ---------------------------------------------------------------------------
__global__ __launch_bounds__(256, 1) void gemm_max_kernel()
{
    extern __shared__ char smem[];
    unsigned* rowmaxU = reinterpret_cast<unsigned*>(smem + RM_OFF);
    const uint32_t smem_u32 = (uint32_t)__cvta_generic_to_shared(smem);

    const int b   = blockIdx.x >> 4;
    const int qt  = blockIdx.x & 15;
    const int tid = threadIdx.x;
    const int lane = tid & 31;
    const int wid  = tid >> 5;
    const int wm = (wid >> 2) * 64;
    const int wn = (wid & 3) * 32;

    if (tid < BM) rowmaxU[tid] = 0u;

    // ---- A tile: 128 x 512 bf16, 8 swizzled 64-col chunks (group 0) ----
    const __nv_bfloat16* gA = g_qn + (size_t)(b * NQ + qt * BM) * DIM;
#pragma unroll
    for (int i = 0; i < 32; i++) {
        int idx = tid + i * 256;         // 0..8191 16B segs
        int r = idx >> 6;                // 64 segs per row
        int rest = idx & 63;
        int ch = rest >> 3;
        int s8 = rest & 7;
        const void* src = gA + (size_t)r * DIM + ch * 64 + s8 * 8;
        cp_async16(smem_u32 + ch * 16384 + swz((uint32_t)(r * 128 + s8 * 16)), src);
    }
    cp_commit();

    const __nv_bfloat16* gB = g_sn + (size_t)b * NS * DIM;

    // prologue: chunks 0, 1
    fill_b_chunk(smem_u32, gB, 0, tid);
    fill_b_chunk(smem_u32, gB, 1, tid);

    float C[4][4][4];
#pragma unroll
    for (int mi = 0; mi < 4; mi++)
#pragma unroll
        for (int ni = 0; ni < 4; ni++)
#pragma unroll
            for (int e = 0; e < 4; e++) C[mi][ni][e] = 0.f;

    float rmax[4][2];
#pragma unroll
    for (int mi = 0; mi < 4; mi++) { rmax[mi][0] = -1e30f; rmax[mi][1] = -1e30f; }

    for (int ci = 0; ci < NCHUNK; ci++) {
        if (ci < NCHUNK - 1) cp_wait<1>(); else cp_wait<0>();
        __syncthreads();
        if (ci + 2 < NCHUNK) fill_b_chunk(smem_u32, gB, ci + 2, tid);

        const int kc = ci & 3;
        const uint32_t bb = A_BYTES + (uint32_t)(ci % NBUF) * BBUF_BYTES;

#pragma unroll
        for (int ksp = 0; ksp < 4; ksp++) {
            const int ks = ksp * 2;
            // B x4 fragments: 2 ksteps per instruction
            unsigned bfr[4][4];
            {
                const int sub = ks >> 2;
                const uint32_t kb = (uint32_t)((ks & 3) * 32
                                  + ((lane >> 3) & 1) * 16 + (lane >> 4) * 32);
#pragma unroll
                for (int ni = 0; ni < 4; ni++) {
                    int n = wn + ni * 8 + (lane & 7);
                    uint32_t addr = smem_u32 + bb + sub * 16384
                                  + swz((uint32_t)(n * 128) + kb);
                    asm volatile("ldmatrix.sync.aligned.m8n8.x4.shared.b16 {%0,%1,%2,%3}, [%4];"
                                 : "=r"(bfr[ni][0]), "=r"(bfr[ni][1]),
                                   "=r"(bfr[ni][2]), "=r"(bfr[ni][3])
                                 : "r"(addr));
                }
            }
#pragma unroll
            for (int h = 0; h < 2; h++) {
                const int kss = ks + h;
                const int ach = kc * 2 + (kss >> 2);
                const uint32_t kb = (uint32_t)((kss & 3) * 32 + (lane >> 4) * 16);
                unsigned afr[4][4];
#pragma unroll
                for (int mi = 0; mi < 4; mi++) {
                    int r = wm + mi * 16 + (lane & 15);
                    uint32_t addr = smem_u32 + ach * 16384
                                  + swz((uint32_t)(r * 128) + kb);
                    asm volatile("ldmatrix.sync.aligned.m8n8.x4.shared.b16 {%0,%1,%2,%3}, [%4];"
                                 : "=r"(afr[mi][0]), "=r"(afr[mi][1]),
                                   "=r"(afr[mi][2]), "=r"(afr[mi][3])
                                 : "r"(addr));
                }
#pragma unroll
                for (int mi = 0; mi < 4; mi++)
#pragma unroll
                    for (int ni = 0; ni < 4; ni++) {
                        asm volatile(
                            "mma.sync.aligned.m16n8k16.row.col.f32.bf16.bf16.f32 "
                            "{%0,%1,%2,%3}, {%4,%5,%6,%7}, {%8,%9}, {%0,%1,%2,%3};"
                            : "+f"(C[mi][ni][0]), "+f"(C[mi][ni][1]),
                              "+f"(C[mi][ni][2]), "+f"(C[mi][ni][3])
                            : "r"(afr[mi][0]), "r"(afr[mi][1]),
                              "r"(afr[mi][2]), "r"(afr[mi][3]),
                              "r"(bfr[ni][2 * h]), "r"(bfr[ni][2 * h + 1]));
                    }
            }
        }

        if (kc == 3) {   // end of s-tile: fold into running row max, reset C
#pragma unroll
            for (int mi = 0; mi < 4; mi++) {
                float m0 = rmax[mi][0], m1 = rmax[mi][1];
#pragma unroll
                for (int ni = 0; ni < 4; ni++) {
                    m0 = fmaxf(m0, fmaxf(C[mi][ni][0], C[mi][ni][1]));
                    m1 = fmaxf(m1, fmaxf(C[mi][ni][2], C[mi][ni][3]));
                    C[mi][ni][0] = 0.f; C[mi][ni][1] = 0.f;
                    C[mi][ni][2] = 0.f; C[mi][ni][3] = 0.f;
                }
                rmax[mi][0] = m0; rmax[mi][1] = m1;
            }
        }
    }

    // epilogue: combine per-row maxes across lanes/warps via smem atomics
#pragma unroll
    for (int mi = 0; mi < 4; mi++) {
#pragma unroll
        for (int g = 0; g < 2; g++) {
            int row = wm + mi * 16 + (lane >> 2) + g * 8;
            atomicMax(&rowmaxU[row], fkey(rmax[mi][g]));
        }
    }
    __syncthreads();
    if (tid < BM)
        g_maxdot[(size_t)b * NQ + qt * BM + tid] = funkey(rowmaxU[tid]);
}

// ---------------------------------------------------------------------------
// Finalize: out[b] = mean over q of (1 - maxdot)
// ---------------------------------------------------------------------------
__global__ void finalize_kernel(float* __restrict__ out)
{
    __shared__ float red[256];
    int b = blockIdx.x;
    float s = 0.f;
    for (int i = threadIdx.x; i < NQ; i += 256)
        s += 1.0f - g_maxdot[(size_t)b * NQ + i];
    red[threadIdx.x] = s;
    __syncthreads();
#pragma unroll
    for (int o = 128; o > 0; o >>= 1) {
        if (threadIdx.x < o) red[threadIdx.x] += red[threadIdx.x + o];
        __syncthreads();
    }
    if (threadIdx.x == 0) out[b] = red[0] * (1.0f / NQ);
}

// ---------------------------------------------------------------------------
extern "C" void kernel_launch(void* const* d_in, const int* in_sizes, int n_in,
                              void* d_out, int out_size)
{
    const float* q = (const float*)d_in[0];
    const float* s = (const float*)d_in[1];
    float* out = (float*)d_out;

    cudaFuncSetAttribute(gemm_max_kernel,
                         cudaFuncAttributeMaxDynamicSharedMemorySize, SMEM_TOTAL);

    const int nrows = BATCH * (NQ + NS);
    normalize_all_kernel<<<(nrows + 7) / 8, 256>>>(q, s);
    gemm_max_kernel<<<BATCH * (NQ / BM), 256, SMEM_TOTAL>>>();
    finalize_kernel<<<BATCH, 256>>>(out);
}